// round 7
// baseline (speedup 1.0000x reference)
#include <cuda_runtime.h>
#include <cstdint>
#include <math.h>

// ---------------- Problem constants ----------------
#define BB   256
#define NH   850
#define TT   70
#define PK   864            // padded K for states (27*32)
#define PK0  1728           // padded K for [x, h]  (54*32)
#define NTHR 128
#define NKT_E 27            // K stages, edge GEMM
#define NKT_0 54            // K stages, init GEMM
#define NTIL_N 27           // N pair-tiles of 32 (864/32)
#define NTIL_M 4            // M tiles of 64 (256/64)
#define TPE (NTIL_M * NTIL_N)   // 108 tiles per edge
#define BLK_FLOATS 2048     // one prepped B block: 32k x 64cols (interleaved) = 8KB

// ---------------- Global scratch (static; no allocs) ----------------
__device__ __align__(16) float g_states [9][BB * PK];   // fp32: residual + mean
__device__ __align__(16) float g_statesT[9][BB * PK];   // tf32-pre-rounded A inputs
__device__ __align__(16) float g_xh[BB * PK0];          // tf32 [x | h]
__device__ __align__(16) float g_hfp[BB * NH];          // fp32 h_prev (gemm0 residual)
// prepped weights: per (nt, kt) an 8KB block [ks(4)][lc(4)][col(64)][hh(2)]
__device__ __align__(16) float g_w0t[(size_t)NTIL_N * NKT_0 * BLK_FLOATS];
__device__ __align__(16) float g_wet[8][(size_t)NTIL_N * NKT_E * BLK_FLOATS];

__device__ unsigned g_cnt = 0;
__device__ unsigned g_tickets[6];
__device__ volatile unsigned g_sense = 0;

struct Edge { int pred, out, w, act; };
__constant__ Edge c_edges[8] = {
    {0, 1, 0, 0}, {1, 2, 1, 1}, {1, 3, 2, 1}, {1, 4, 3, 3},
    {2, 5, 4, 0}, {5, 6, 5, 2}, {3, 7, 6, 0}, {5, 8, 7, 1},
};
__constant__ int c_lvl_n[4]    = {1, 3, 2, 2};
__constant__ int c_lvl_e[4][3] = {{0,0,0}, {1,2,3}, {4,6,0}, {5,7,0}};

// ---------------- Helpers ----------------
__device__ __forceinline__ uint32_t cvt_tf32(float x) {
    uint32_t u;
    asm("cvt.rna.tf32.f32 %0, %1;" : "=r"(u) : "f"(x));
    return u;
}
__device__ __forceinline__ float tf32r(float x) { return __uint_as_float(cvt_tf32(x)); }

__device__ __forceinline__ void cp16(void* dst, const void* src) {
    uint32_t d = (uint32_t)__cvta_generic_to_shared(dst);
    asm volatile("cp.async.cg.shared.global [%0], [%1], 16;" :: "r"(d), "l"(src) : "memory");
}
__device__ __forceinline__ void cp_commit() {
    asm volatile("cp.async.commit_group;" ::: "memory");
}
template <int N> __device__ __forceinline__ void cp_wait() {
    asm volatile("cp.async.wait_group %0;" :: "n"(N) : "memory");
}
__device__ __forceinline__ void mma8(float* d, const uint32_t* a, uint32_t b0, uint32_t b1) {
    asm volatile("mma.sync.aligned.m16n8k8.row.col.f32.tf32.tf32.f32 "
        "{%0,%1,%2,%3}, {%4,%5,%6,%7}, {%8,%9}, {%0,%1,%2,%3};"
        : "+f"(d[0]), "+f"(d[1]), "+f"(d[2]), "+f"(d[3])
        : "r"(a[0]), "r"(a[1]), "r"(a[2]), "r"(a[3]), "r"(b0), "r"(b1));
}
__device__ __forceinline__ float actf(float x, int a) {
    if (a == 0) return tanhf(x);
    if (a == 1) return fmaxf(x, 0.f);
    if (a == 2) return 1.f / (1.f + __expf(-x));
    return x;
}

// ---------------- Grid-wide barrier (gridDim-counted; resets tickets) ----------------
__device__ __forceinline__ void grid_sync(unsigned* sense) {
    __syncthreads();
    if (threadIdx.x == 0) {
        unsigned s = *sense + 1;
        *sense = s;
        __threadfence();
        unsigned arr = atomicAdd(&g_cnt, 1u);
        if (arr == gridDim.x - 1) {
            #pragma unroll
            for (int i = 0; i < 6; i++) g_tickets[i] = 0;
            g_cnt = 0;
            __threadfence();
            g_sense = s;
        } else {
            while (g_sense != s) { __nanosleep(64); }
        }
        __threadfence();
    }
    __syncthreads();
}

// ---------------- SMEM layout ----------------
// A: [2][64][36] floats (9216B/stage).  B: [2][16][76] float2 (9728B/stage).
#define ASTRIDE 36
#define BSTRIDE 76          // float2 units per (ks,lc) row; 64 used, 12 pad

__device__ __forceinline__ void load_stage(
    float (*As)[64][ASTRIDE], float2 (*Bs)[16][BSTRIDE], int s, int kt,
    const float* __restrict__ A, int strideA, const float* __restrict__ Wnt,
    int m0, int tid)
{
    const int k0 = kt * 32;
    #pragma unroll
    for (int i = 0; i < 4; i++) {
        int idx = tid + i * 128;
        int r = idx >> 3, c = idx & 7;
        cp16(&As[s][r][c * 4], A + (size_t)(m0 + r) * strideA + k0 + c * 4);
    }
    const float* wb = Wnt + (size_t)kt * BLK_FLOATS;
    float* bdst = (float*)&Bs[s][0][0];
    #pragma unroll
    for (int i = 0; i < 4; i++) {
        int c = tid + i * 128;           // 512 chunks of 4 floats
        int row = c >> 5, w = c & 31;    // 16 rows x 128 floats
        cp16(bdst + row * (BSTRIDE * 2) + w * 4, wb + c * 4);
    }
}

// ---------------- One GEMM tile: 64 rows x 32 col-pairs ----------------
// A pre-rounded tf32. B pre-interleaved ((k,k+4) adjacent). Fused highway epilogue.
__device__ __forceinline__ void gemm_tile(
    float (*As)[64][ASTRIDE], float2 (*Bs)[16][BSTRIDE],
    const float* __restrict__ A, int strideA, const float* __restrict__ Wnt,
    const float* __restrict__ P, int strideP,
    float* __restrict__ Out, float* __restrict__ OutT,
    int act, int niter, int m0, int j0)
{
    const int tid = threadIdx.x, wid = tid >> 5, lid = tid & 31;
    const int wm = wid & 1, wn = wid >> 1;      // 2(M) x 2(N) warps
    const int lr = lid >> 2, lc = lid & 3;

    float cacc[2][2][4], hacc[2][2][4];
    #pragma unroll
    for (int a = 0; a < 2; a++)
        #pragma unroll
        for (int b = 0; b < 2; b++)
            #pragma unroll
            for (int c = 0; c < 4; c++) { cacc[a][b][c] = 0.f; hacc[a][b][c] = 0.f; }

    load_stage(As, Bs, 0, 0, A, strideA, Wnt, m0, tid);
    cp_commit();

    for (int it = 0; it < niter; it++) {
        const int buf = it & 1;
        if (it + 1 < niter) {
            load_stage(As, Bs, buf ^ 1, it + 1, A, strideA, Wnt, m0, tid);
            cp_commit();
            cp_wait<1>();
        } else {
            cp_wait<0>();
        }
        __syncthreads();

        #pragma unroll
        for (int ks = 0; ks < 4; ks++) {
            const int k = ks * 8 + lc;
            uint32_t af[2][4];
            #pragma unroll
            for (int mf = 0; mf < 2; mf++) {
                const int r = wm * 32 + mf * 16 + lr;
                af[mf][0] = __float_as_uint(As[buf][r][k]);
                af[mf][1] = __float_as_uint(As[buf][r + 8][k]);
                af[mf][2] = __float_as_uint(As[buf][r][k + 4]);
                af[mf][3] = __float_as_uint(As[buf][r + 8][k + 4]);
            }
            const int brow = ks * 4 + lc;
            #pragma unroll
            for (int nf = 0; nf < 2; nf++) {
                const int col = wn * 16 + nf * 8 + lr;
                float2 bc = Bs[buf][brow][col];
                float2 bh = Bs[buf][brow][col + 32];
                #pragma unroll
                for (int mf = 0; mf < 2; mf++) {
                    mma8(cacc[mf][nf], af[mf], __float_as_uint(bc.x), __float_as_uint(bc.y));
                    mma8(hacc[mf][nf], af[mf], __float_as_uint(bh.x), __float_as_uint(bh.y));
                }
            }
        }
        __syncthreads();
    }

    #pragma unroll
    for (int mf = 0; mf < 2; mf++) {
        #pragma unroll
        for (int nf = 0; nf < 2; nf++) {
            const int c0 = j0 + wn * 16 + nf * 8 + lc * 2;
            #pragma unroll
            for (int e = 0; e < 4; e++) {
                int r = m0 + wm * 32 + mf * 16 + lr + (e >> 1) * 8;
                int c = c0 + (e & 1);
                if (c < NH) {
                    float sp = P[(size_t)r * strideP + c];
                    float g  = 1.f / (1.f + __expf(-cacc[mf][nf][e]));
                    float av = actf(hacc[mf][nf][e], act);
                    float v  = sp + g * (av - sp);
                    Out [(size_t)r * PK + c] = v;
                    OutT[(size_t)r * PK + c] = tf32r(v);
                }
            }
        }
    }
}

// ---------------- Persistent kernel ----------------
__global__ __launch_bounds__(NTHR, 4) void step_kernel(
    const float* __restrict__ inputs, const float* __restrict__ hidden,
    float* __restrict__ out)
{
    __shared__ float  As[2][64][ASTRIDE];
    __shared__ float2 Bs[2][16][BSTRIDE];
    __shared__ int s_tile;

    unsigned sense = g_sense;   // monotonic; replay-safe
    const int tid = threadIdx.x;
    const int gstride = gridDim.x * NTHR;
    const int gtid = blockIdx.x * NTHR + tid;

    for (int i = gtid; i < BB * NH; i += gstride) {
        int b = i / NH, j = i % NH;
        g_xh[b * PK0 + j]      = tf32r(inputs[i]);
        g_xh[b * PK0 + PK + j] = tf32r(hidden[i]);
        g_hfp[i] = hidden[i];
    }
    grid_sync(&sense);

    for (int t = 0; t < TT; t++) {
        // Level 0: s0 = highway([x,h] @ W0); 108 tiles, 54 K-stages
        for (;;) {
            __syncthreads();
            if (tid == 0) s_tile = atomicAdd(&g_tickets[0], 1);
            __syncthreads();
            int tl = s_tile;
            if (tl >= TPE) break;
            int mt = tl / NTIL_N, nt = tl % NTIL_N;
            gemm_tile(As, Bs, g_xh, PK0,
                      g_w0t + (size_t)nt * NKT_0 * BLK_FLOATS,
                      g_hfp, NH, g_states[0], g_statesT[0],
                      0, NKT_0, mt * 64, nt * 32);
        }
        grid_sync(&sense);

        // Levels 1..4: edge GEMMs, 27 K-stages
        for (int L = 0; L < 4; L++) {
            const int ntiles = c_lvl_n[L] * TPE;
            for (;;) {
                __syncthreads();
                if (tid == 0) s_tile = atomicAdd(&g_tickets[1 + L], 1);
                __syncthreads();
                int tl = s_tile;
                if (tl >= ntiles) break;
                Edge E = c_edges[c_lvl_e[L][tl / TPE]];
                int r = tl % TPE;
                int mt = r / NTIL_N, nt = r % NTIL_N;
                gemm_tile(As, Bs, g_statesT[E.pred], PK,
                          g_wet[E.w] + (size_t)nt * NKT_E * BLK_FLOATS,
                          g_states[E.pred], PK, g_states[E.out], g_statesT[E.out],
                          E.act, NKT_E, mt * 64, nt * 32);
            }
            grid_sync(&sense);
        }

        // mean over s1..s8 -> out[t]; stage next x/h
        for (int i = gtid; i < BB * NH; i += gstride) {
            int b = i / NH, j = i % NH;
            float s = 0.f;
            #pragma unroll
            for (int st = 1; st < 9; st++) s += g_states[st][b * PK + j];
            s *= 0.125f;
            out[(size_t)t * (BB * NH) + i] = s;
            g_hfp[i] = s;
            g_xh[b * PK0 + PK + j] = tf32r(s);
            if (t + 1 < TT) g_xh[b * PK0 + j] = tf32r(inputs[(size_t)(t + 1) * (BB * NH) + i]);
            else            out[(size_t)TT * (BB * NH) + i] = s;   // hiddens[-1]
        }
        grid_sync(&sense);
    }
}

// ---------------- Weight prep: B blocks in mma-fragment-interleaved layout ----------------
// Block (nt, kt): pos = ((ks*4+lc)*64 + col)*2 + hh; local k = ks*8+lc+4*hh;
// col<32 -> weight col nt*32+col (c half); col>=32 -> 850 + nt*32 + col-32 (h half).
__global__ void prep_w0(const float* __restrict__ W0) {
    size_t i = (size_t)blockIdx.x * blockDim.x + threadIdx.x;
    if (i >= (size_t)NTIL_N * NKT_0 * BLK_FLOATS) return;
    int blk = (int)(i / BLK_FLOATS), pos = (int)(i % BLK_FLOATS);
    int nt = blk / NKT_0, kt = blk % NKT_0;
    int hh = pos & 1, col = (pos >> 1) & 63, lc = (pos >> 7) & 3, ks = pos >> 9;
    int p = kt * 32 + ks * 8 + lc + 4 * hh;     // padded K index (0..1727)
    int kr = (p < NH) ? p : ((p >= PK && p < PK + NH) ? (NH + p - PK) : -1);
    int j = nt * 32 + (col & 31);
    int wc = (j < NH) ? ((col < 32) ? j : NH + j) : -1;
    float v = 0.f;
    if (kr >= 0 && wc >= 0) v = W0[(size_t)kr * (2 * NH) + wc];
    g_w0t[i] = tf32r(v);
}
__global__ void prep_we(const float* __restrict__ Ws) {
    size_t i = (size_t)blockIdx.x * blockDim.x + threadIdx.x;
    if (i >= (size_t)8 * NTIL_N * NKT_E * BLK_FLOATS) return;
    int e = (int)(i / ((size_t)NTIL_N * NKT_E * BLK_FLOATS));
    size_t rm = i % ((size_t)NTIL_N * NKT_E * BLK_FLOATS);
    int blk = (int)(rm / BLK_FLOATS), pos = (int)(rm % BLK_FLOATS);
    int nt = blk / NKT_E, kt = blk % NKT_E;
    int hh = pos & 1, col = (pos >> 1) & 63, lc = (pos >> 7) & 3, ks = pos >> 9;
    int p = kt * 32 + ks * 8 + lc + 4 * hh;     // padded K index (0..863)
    int j = nt * 32 + (col & 31);
    int wc = (j < NH) ? ((col < 32) ? j : NH + j) : -1;
    float v = 0.f;
    if (p < NH && wc >= 0) v = Ws[((size_t)e * NH + p) * (2 * NH) + wc];
    g_wet[e][(size_t)blk * BLK_FLOATS + pos] = tf32r(v);
}

// ---------------- Zero padding + barrier/ticket state ----------------
__global__ void zero_kernel() {
    int i = blockIdx.x * blockDim.x + threadIdx.x;
    if (i == 0) {
        g_cnt = 0;
        for (int j = 0; j < 6; j++) g_tickets[j] = 0;
    }
    if (i < 9 * BB * PK) {
        (&g_states[0][0])[i]  = 0.f;
        (&g_statesT[0][0])[i] = 0.f;
    }
    if (i < BB * PK0) g_xh[i] = 0.f;
}

// ---------------- Host ----------------
extern "C" void kernel_launch(void* const* d_in, const int* in_sizes, int n_in,
                              void* d_out, int out_size)
{
    const float* inputs = (const float*)d_in[0];  // [T, B, NH]
    const float* hidden = (const float*)d_in[1];  // [1, B, NH]
    const float* W0     = (const float*)d_in[2];  // [2*NH, 2*NH]
    const float* Ws     = (const float*)d_in[3];  // [8, NH, 2*NH]
    float* out = (float*)d_out;

    zero_kernel<<<(9 * BB * PK + 255) / 256, 256>>>();
    prep_w0<<<(int)(((size_t)NTIL_N * NKT_0 * BLK_FLOATS + 255) / 256), 256>>>(W0);
    prep_we<<<(int)(((size_t)8 * NTIL_N * NKT_E * BLK_FLOATS + 255) / 256), 256>>>(Ws);

    // Grid sized from real occupancy so the spin barrier can never deadlock.
    int dev = 0, nsm = 148, mab = 1;
    cudaGetDevice(&dev);
    cudaDeviceGetAttribute(&nsm, cudaDevAttrMultiProcessorCount, dev);
    cudaOccupancyMaxActiveBlocksPerMultiprocessor(&mab, step_kernel, NTHR, 0);
    if (mab < 1) mab = 1;
    if (mab > 6) mab = 6;
    int ncta = nsm * mab;

    step_kernel<<<ncta, NTHR>>>(inputs, hidden, out);
}

// round 8
// speedup vs baseline: 2.6354x; 2.6354x over previous
#include <cuda_runtime.h>
#include <cuda_bf16.h>
#include <cstdint>
#include <math.h>

// ---------------- Problem constants ----------------
#define BB   256
#define NH   850
#define TT   70
#define PK   896            // padded K for states (14*64)
#define PK0  1792           // padded K for [x, h]  (28*64)
#define BK   64
#define NKT_E 14            // K stages, edge GEMM
#define NKT_0 28            // K stages, init GEMM
#define NTIL_N 27           // N pair-tiles of 32
#define BLK_HALFS 4096      // one packed B block: 64k x 64cols bf16 = 8KB

// ---------------- Global scratch (static; no allocs) ----------------
__device__ __align__(16) float         g_statesF[9][BB * PK];  // fp32 residual/mean
__device__ __align__(16) __nv_bfloat16 g_statesB[9][BB * PK];  // bf16 GEMM A operand
__device__ __align__(16) __nv_bfloat16 g_xh[BB * PK0];         // bf16 [x | h]
__device__ __align__(16) float         g_hfp[BB * NH];         // fp32 h_prev
__device__ __align__(16) __nv_bfloat16 g_w0t[(size_t)NTIL_N * NKT_0 * BLK_HALFS];
__device__ __align__(16) __nv_bfloat16 g_wet[8][(size_t)NTIL_N * NKT_E * BLK_HALFS];

struct Edge { int pred, out, w, act; };
__constant__ Edge c_edges[8] = {
    {0, 1, 0, 0}, {1, 2, 1, 1}, {1, 3, 2, 1}, {1, 4, 3, 3},
    {2, 5, 4, 0}, {5, 6, 5, 2}, {3, 7, 6, 0}, {5, 8, 7, 1},
};

// ---------------- Helpers ----------------
__device__ __forceinline__ void cp16(void* dst, const void* src) {
    uint32_t d = (uint32_t)__cvta_generic_to_shared(dst);
    asm volatile("cp.async.cg.shared.global [%0], [%1], 16;" :: "r"(d), "l"(src) : "memory");
}
__device__ __forceinline__ void cp_commit() {
    asm volatile("cp.async.commit_group;" ::: "memory");
}
template <int N> __device__ __forceinline__ void cp_wait() {
    asm volatile("cp.async.wait_group %0;" :: "n"(N) : "memory");
}
__device__ __forceinline__ void ldsm4(uint32_t* a, uint32_t addr) {
    asm volatile("ldmatrix.sync.aligned.m8n8.x4.shared.b16 {%0,%1,%2,%3}, [%4];"
        : "=r"(a[0]), "=r"(a[1]), "=r"(a[2]), "=r"(a[3]) : "r"(addr));
}
__device__ __forceinline__ void mma16(float* d, const uint32_t* a, uint32_t b0, uint32_t b1) {
    asm volatile("mma.sync.aligned.m16n8k16.row.col.f32.bf16.bf16.f32 "
        "{%0,%1,%2,%3}, {%4,%5,%6,%7}, {%8,%9}, {%0,%1,%2,%3};"
        : "+f"(d[0]), "+f"(d[1]), "+f"(d[2]), "+f"(d[3])
        : "r"(a[0]), "r"(a[1]), "r"(a[2]), "r"(a[3]), "r"(b0), "r"(b1));
}
__device__ __forceinline__ float actf(float x, int a) {
    if (a == 0) return tanhf(x);
    if (a == 1) return fmaxf(x, 0.f);
    if (a == 2) return 1.f / (1.f + __expf(-x));
    return x;
}

// ---------------- GEMM core: tile 64 rows x 32 col-pairs, 256 threads ----------------
// Warp grid 2(M) x 4(N); warp tile 32 rows x 8 pairs. A bf16 row-major (ldmatrix),
// B pre-packed in mma-fragment order (one LDS.64 per fragment). Fused highway epilogue.
__device__ __forceinline__ void gemm_core(
    const __nv_bfloat16* __restrict__ A, int strideA,
    const __nv_bfloat16* __restrict__ Wblk,           // (nt)'s blocks; + kt*BLK_HALFS
    const float* __restrict__ P, int strideP,
    float* __restrict__ OutF, __nv_bfloat16* __restrict__ OutB,
    int act, int niter, int m0, int j0)
{
    __shared__ __nv_bfloat16 As[2][64][72];   // 144B row stride (conflict-free LDSM)
    __shared__ __nv_bfloat16 Bs[2][BLK_HALFS];

    const int tid = threadIdx.x, wid = tid >> 5, lid = tid & 31;
    const int wm = wid & 1, wn = wid >> 1;    // 2 x 4 warp grid
    const int lr = lid >> 2, lc = lid & 3;

    float cacc[2][4] = {}, hacc[2][4] = {};

    // stage loader: A 64x64 bf16 (8KB) + B block (8KB), 4 cp16/thread
    auto load = [&](int s, int kt) {
        #pragma unroll
        for (int i = 0; i < 2; i++) {
            int idx = tid + i * 256;
            int r = idx >> 3, c = idx & 7;
            cp16(&As[s][r][c * 8], A + (size_t)(m0 + r) * strideA + kt * 64 + c * 8);
        }
        const __nv_bfloat16* wb = Wblk + (size_t)kt * BLK_HALFS;
        #pragma unroll
        for (int i = 0; i < 2; i++) {
            int idx = tid + i * 256;
            cp16(&Bs[s][idx * 8], wb + idx * 8);
        }
        cp_commit();
    };

    load(0, 0);

    for (int it = 0; it < niter; it++) {
        const int buf = it & 1;
        if (it + 1 < niter) { load(buf ^ 1, it + 1); cp_wait<1>(); }
        else                { cp_wait<0>(); }
        __syncthreads();

        const uint32_t abase = (uint32_t)__cvta_generic_to_shared(&As[buf][0][0]);
        // ldmatrix lane addressing: lanes 0-7 rows 0-7 (k-half 0), 8-15 rows 8-15,
        // 16-23 rows 0-7 (k-half 1, +16B), 24-31 rows 8-15 (+16B)
        const uint32_t arow = abase + (uint32_t)(wm * 32 + (lid & 15)) * 144
                                    + (uint32_t)(lid >> 4) * 16;
        const __nv_bfloat16* bb = &Bs[buf][0];

        #pragma unroll
        for (int ks = 0; ks < 4; ks++) {
            uint32_t a0[4], a1[4];
            ldsm4(a0, arow + ks * 32);
            ldsm4(a1, arow + 16 * 144 + ks * 32);
            const uint2 bc = *(const uint2*)(bb + ((ks * 8 + wn) * 32 + lid) * 4);
            const uint2 bh = *(const uint2*)(bb + ((ks * 8 + wn) * 32 + lid) * 4 + 512);
            mma16(cacc[0], a0, bc.x, bc.y);
            mma16(hacc[0], a0, bh.x, bh.y);
            mma16(cacc[1], a1, bc.x, bc.y);
            mma16(hacc[1], a1, bh.x, bh.y);
        }
        __syncthreads();
    }

    // fused highway epilogue; dual-write fp32 + bf16
    #pragma unroll
    for (int mf = 0; mf < 2; mf++) {
        const int r0 = m0 + wm * 32 + mf * 16 + lr;
        const int c0 = j0 + wn * 8 + lc * 2;
        #pragma unroll
        for (int e = 0; e < 4; e++) {
            int r = r0 + (e >> 1) * 8;
            int c = c0 + (e & 1);
            if (c < NH) {
                float sp = P[(size_t)r * strideP + c];
                float g  = 1.f / (1.f + __expf(-cacc[mf][e]));
                float av = actf(hacc[mf][e], act);
                float v  = sp + g * (av - sp);
                OutF[(size_t)r * PK + c] = v;
                OutB[(size_t)r * PK + c] = __float2bfloat16_rn(v);
            }
        }
    }
}

__global__ __launch_bounds__(256) void gemm0_kernel() {
    gemm_core(g_xh, PK0,
              g_w0t + (size_t)blockIdx.x * NKT_0 * BLK_HALFS,
              g_hfp, NH, g_statesF[0], g_statesB[0],
              0, NKT_0, blockIdx.y * 64, blockIdx.x * 32);
}
__global__ __launch_bounds__(256) void edge_kernel(int e0, int e1, int e2) {
    int e = (blockIdx.z == 0) ? e0 : ((blockIdx.z == 1) ? e1 : e2);
    Edge E = c_edges[e];
    gemm_core(g_statesB[E.pred], PK,
              g_wet[E.w] + (size_t)blockIdx.x * NKT_E * BLK_HALFS,
              g_statesF[E.pred], PK, g_statesF[E.out], g_statesB[E.out],
              E.act, NKT_E, blockIdx.y * 64, blockIdx.x * 32);
}

// ---------------- mean + stage next x/h ----------------
__global__ void mean_kernel(const float* __restrict__ inputs, float* __restrict__ out, int t) {
    int i = blockIdx.x * blockDim.x + threadIdx.x;
    if (i < BB * NH) {
        int b = i / NH, j = i % NH;
        float s = 0.f;
        #pragma unroll
        for (int st = 1; st < 9; st++) s += g_statesF[st][b * PK + j];
        s *= 0.125f;
        out[(size_t)t * (BB * NH) + i] = s;
        g_hfp[i] = s;
        g_xh[b * PK0 + PK + j] = __float2bfloat16_rn(s);
        if (t + 1 < TT) g_xh[b * PK0 + j] =
            __float2bfloat16_rn(inputs[(size_t)(t + 1) * (BB * NH) + i]);
        else out[(size_t)TT * (BB * NH) + i] = s;   // hiddens[-1]
    }
}
__global__ void stage0_kernel(const float* __restrict__ x0, const float* __restrict__ h0) {
    int i = blockIdx.x * blockDim.x + threadIdx.x;
    if (i < BB * NH) {
        int b = i / NH, j = i % NH;
        g_xh[b * PK0 + j]      = __float2bfloat16_rn(x0[i]);
        g_xh[b * PK0 + PK + j] = __float2bfloat16_rn(h0[i]);
        g_hfp[i] = h0[i];
    }
}

// ---------------- Weight prep: packed B fragment blocks ----------------
// Block (nt, kt): pos = ((ks*8+g)*32 + lane)*4 + r*2 + hh.
// lane -> (lr=lane>>2, lc=lane&3); local k = ks*16 + 2*lc + 8*r + hh;
// g<4: c-col nt*32+g*8+lr; g>=4: h-col 850 + nt*32 + (g-4)*8 + lr.
__global__ void prep_w0(const float* __restrict__ W0) {
    size_t i = (size_t)blockIdx.x * blockDim.x + threadIdx.x;
    if (i >= (size_t)NTIL_N * NKT_0 * BLK_HALFS) return;
    int blk = (int)(i >> 12), pos = (int)(i & 4095);
    int nt = blk / NKT_0, kt = blk % NKT_0;
    int hh = pos & 1, rr = (pos >> 1) & 1, lane = (pos >> 2) & 31;
    int g = (pos >> 7) & 7, ks = (pos >> 10) & 3;
    int lcc = lane & 3, lrr = lane >> 2;
    int p = kt * 64 + ks * 16 + 2 * lcc + 8 * rr + hh;            // 0..1791
    int kr = (p < NH) ? p : ((p >= PK && p < PK + NH) ? (NH + p - PK) : -1);
    int jj = nt * 32 + (g & 3) * 8 + lrr;
    float v = 0.f;
    if (kr >= 0 && jj < NH) {
        int wc = (g < 4) ? jj : NH + jj;
        v = W0[(size_t)kr * (2 * NH) + wc];
    }
    g_w0t[i] = __float2bfloat16_rn(v);
}
__global__ void prep_we(const float* __restrict__ Ws) {
    size_t i = (size_t)blockIdx.x * blockDim.x + threadIdx.x;
    if (i >= (size_t)8 * NTIL_N * NKT_E * BLK_HALFS) return;
    int e = (int)(i / ((size_t)NTIL_N * NKT_E * BLK_HALFS));
    size_t rm = i % ((size_t)NTIL_N * NKT_E * BLK_HALFS);
    int blk = (int)(rm >> 12), pos = (int)(rm & 4095);
    int nt = blk / NKT_E, kt = blk % NKT_E;
    int hh = pos & 1, rr = (pos >> 1) & 1, lane = (pos >> 2) & 31;
    int g = (pos >> 7) & 7, ks = (pos >> 10) & 3;
    int lcc = lane & 3, lrr = lane >> 2;
    int p = kt * 64 + ks * 16 + 2 * lcc + 8 * rr + hh;            // 0..895
    int jj = nt * 32 + (g & 3) * 8 + lrr;
    float v = 0.f;
    if (p < NH && jj < NH) {
        int wc = (g < 4) ? jj : NH + jj;
        v = Ws[((size_t)e * NH + p) * (2 * NH) + wc];
    }
    g_wet[e][rm] = __float2bfloat16_rn(v);
}

// ---------------- Zero bf16 padding ----------------
__global__ void zero_kernel() {
    int i = blockIdx.x * blockDim.x + threadIdx.x;
    if (i < 9 * BB * PK) (&g_statesB[0][0])[i] = __float2bfloat16_rn(0.f);
    if (i < BB * PK0)    g_xh[i] = __float2bfloat16_rn(0.f);
}

// ---------------- Host ----------------
extern "C" void kernel_launch(void* const* d_in, const int* in_sizes, int n_in,
                              void* d_out, int out_size)
{
    const float* inputs = (const float*)d_in[0];  // [T, B, NH]
    const float* hidden = (const float*)d_in[1];  // [1, B, NH]
    const float* W0     = (const float*)d_in[2];  // [2*NH, 2*NH]
    const float* Ws     = (const float*)d_in[3];  // [8, NH, 2*NH]
    float* out = (float*)d_out;

    zero_kernel<<<(9 * BB * PK + 255) / 256, 256>>>();
    prep_w0<<<(int)(((size_t)NTIL_N * NKT_0 * BLK_HALFS + 255) / 256), 256>>>(W0);
    prep_we<<<(int)(((size_t)8 * NTIL_N * NKT_E * BLK_HALFS + 255) / 256), 256>>>(Ws);
    stage0_kernel<<<(BB * NH + 255) / 256, 256>>>(inputs, hidden);

    const dim3 blk(256);
    for (int t = 0; t < TT; t++) {
        gemm0_kernel<<<dim3(NTIL_N, 4, 1), blk>>>();
        edge_kernel<<<dim3(NTIL_N, 4, 1), blk>>>(0, 0, 0);
        edge_kernel<<<dim3(NTIL_N, 4, 3), blk>>>(1, 2, 3);
        edge_kernel<<<dim3(NTIL_N, 4, 2), blk>>>(4, 6, 0);
        edge_kernel<<<dim3(NTIL_N, 4, 2), blk>>>(5, 7, 0);
        mean_kernel<<<(BB * NH + 255) / 256, 256>>>(inputs, out, t);
    }
}